// round 7
// baseline (speedup 1.0000x reference)
#include <cuda_runtime.h>
#include <cuda_bf16.h>
#include <cstdint>

// Problem constants
#define BB 4
#define TT 4096
#define CC 1024
#define HH 64
#define MM (BB * TT)          // 16384 rows

#define SM_SCALE_LOG2E (0.03125f * 1.4426950408889634f)

// ---------------------------------------------------------------------------
// Global scratch
// ---------------------------------------------------------------------------
__device__ uint4  g_qhi4[MM * HH * 2 / 16];   // bf16 [m][64]
__device__ uint4  g_qlo4[MM * HH * 2 / 16];
__device__ uint4  g_khi4[MM * HH * 2 / 16];
__device__ uint4  g_klo4[MM * HH * 2 / 16];
__device__ uint4  g_vthi4[MM * HH * 2 / 16];  // bf16 [b][h][t]
__device__ uint4  g_vtlo4[MM * HH * 2 / 16];
__device__ uint4  g_wthi4[192 * CC * 2 / 16]; // bf16 Wt [n=192][k=1024]
__device__ uint4  g_wtlo4[192 * CC * 2 / 16];
__device__ float  g_oacc[MM * HH];            // fp32 un-normalized O
__device__ float  g_lacc[MM];                 // fp32 row sums

__device__ __forceinline__ float fast_ex2(float x) {
    float y;
    asm("ex2.approx.ftz.f32 %0, %1;" : "=f"(y) : "f"(x));
    return y;
}
__device__ __forceinline__ uint32_t smem_u32(const void* p) {
    uint32_t a;
    asm("{ .reg .u64 t; cvta.to.shared.u64 t, %1; cvt.u32.u64 %0, t; }"
        : "=r"(a) : "l"(p));
    return a;
}
__device__ __forceinline__ void ldsm4(uint32_t* r, uint32_t addr) {
    asm volatile("ldmatrix.sync.aligned.m8n8.x4.shared.b16 {%0,%1,%2,%3}, [%4];"
                 : "=r"(r[0]), "=r"(r[1]), "=r"(r[2]), "=r"(r[3]) : "r"(addr));
}
__device__ __forceinline__ void mma16816(float* d, const uint32_t* a,
                                         uint32_t b0, uint32_t b1) {
    asm volatile("mma.sync.aligned.m16n8k16.row.col.f32.bf16.bf16.f32 "
                 "{%0,%1,%2,%3}, {%4,%5,%6,%7}, {%8,%9}, {%0,%1,%2,%3};"
                 : "+f"(d[0]), "+f"(d[1]), "+f"(d[2]), "+f"(d[3])
                 : "r"(a[0]), "r"(a[1]), "r"(a[2]), "r"(a[3]), "r"(b0), "r"(b1));
}
__device__ __forceinline__ void cp16(uint32_t dst, const void* src) {
    asm volatile("cp.async.cg.shared.global [%0], [%1], 16;"
                 :: "r"(dst), "l"(src));
}
#define CP_COMMIT() asm volatile("cp.async.commit_group;" ::: "memory")
#define CP_WAIT1()  asm volatile("cp.async.wait_group 1;" ::: "memory")
__device__ __forceinline__ uint32_t packbf2(float lo, float hi) {
    uint32_t r;
    asm("cvt.rn.bf16x2.f32 %0, %1, %2;" : "=r"(r) : "f"(hi), "f"(lo));
    return r;
}
__device__ __forceinline__ float bf16rt(float x) {
    return __bfloat162float(__float2bfloat16_rn(x));
}

// ---------------------------------------------------------------------------
// prep_w: split+transpose W into Wt hi/lo bf16 [n=mat*64+h][k=1024]
// ---------------------------------------------------------------------------
__global__ __launch_bounds__(256) void prep_w(
    const float* __restrict__ Wq, const float* __restrict__ Wk,
    const float* __restrict__ Wv)
{
    __shared__ float ws[64][65];
    const int kc  = blockIdx.x;          // 0..15 (64-k slabs)
    const int mat = blockIdx.y;
    const float* __restrict__ W = (mat == 0) ? Wq : (mat == 1) ? Wk : Wv;
    const int t = threadIdx.x;
    __nv_bfloat16* wth = (__nv_bfloat16*)g_wthi4;
    __nv_bfloat16* wtl = (__nv_bfloat16*)g_wtlo4;

#pragma unroll
    for (int i = 0; i < 16; i++) {
        int idx = t + i * 256;
        int kk = idx >> 6, h = idx & 63;
        ws[kk][h] = W[(size_t)(kc * 64 + kk) * HH + h];
    }
    __syncthreads();
#pragma unroll
    for (int i = 0; i < 16; i++) {
        int idx = t + i * 256;
        int h = idx >> 6, kk = idx & 63;
        float v = ws[kk][h];
        float hb = bf16rt(v);
        size_t o = (size_t)(mat * 64 + h) * CC + kc * 64 + kk;
        wth[o] = __float2bfloat16_rn(hb);
        wtl[o] = __float2bfloat16_rn(v - hb);
    }
}

// ---------------------------------------------------------------------------
// qkv3: fused tensorized projection. [16384 x 1024] @ [1024 x 192].
// 64-row tiles -> 256 CTAs, 2 CTAs/SM. 8 warps = 4 row x 2 col,
// each warp m16 x n96, acc 48 regs. k-chunk 32, split-bf16 3-pass.
// ---------------------------------------------------------------------------
#define QP 80                 // row pitch in bytes (40 bf16)
#define QKV_ROWS 64
#define AS_BYTES (QKV_ROWS * QP)            // 5120
#define WS_BYTES (192 * QP)                 // 15360
#define OFF_A(buf, sp) ((((buf) * 2 + (sp)) * AS_BYTES))
#define OFF_W(buf, sp) ((4 * AS_BYTES) + (((buf) * 2 + (sp)) * WS_BYTES))
#define QKV3_SMEM (4 * AS_BYTES + 4 * WS_BYTES)   // 81920

__global__ __launch_bounds__(256, 2) void qkv3_kernel(const float* __restrict__ x)
{
    extern __shared__ char smem[];
    const uint32_t sb = smem_u32(smem);
    const int tid  = threadIdx.x;
    const int wid  = tid >> 5;
    const int lane = tid & 31;
    const int wr   = wid >> 1;            // 0..3: rows wr*16
    const int wc   = wid & 1;             // 0..1: cols wc*96
    const int row0 = blockIdx.x * QKV_ROWS;

    const __nv_bfloat16* wth = (const __nv_bfloat16*)g_wthi4;
    const __nv_bfloat16* wtl = (const __nv_bfloat16*)g_wtlo4;

    float acc[12][4];
#pragma unroll
    for (int j = 0; j < 12; j++)
#pragma unroll
        for (int e = 0; e < 4; e++) acc[j][e] = 0.f;

    // A staging: 64 rows x 32 k fp32 per chunk = 512 float4; 2 per thread
    const int akq = tid & 7, ar = tid >> 3;        // ar 0..31
    float4 areg[2];
    auto ldgA = [&](int k0) {
#pragma unroll
        for (int it = 0; it < 2; it++)
            areg[it] = *(const float4*)&x[(size_t)(row0 + ar + 32 * it) * CC +
                                          k0 + akq * 4];
    };
    auto stsA = [&](int buf) {
#pragma unroll
        for (int it = 0; it < 2; it++) {
            float4 v = areg[it];
            float hx = bf16rt(v.x), hy = bf16rt(v.y);
            float hz = bf16rt(v.z), hw = bf16rt(v.w);
            uint32_t off = (uint32_t)((ar + 32 * it) * QP + akq * 8);
            *(uint2*)(smem + OFF_A(buf, 0) + off) =
                make_uint2(packbf2(hx, hy), packbf2(hz, hw));
            *(uint2*)(smem + OFF_A(buf, 1) + off) =
                make_uint2(packbf2(v.x - hx, v.y - hy),
                           packbf2(v.z - hz, v.w - hw));
        }
    };
    auto cpW = [&](int buf, int k0) {
#pragma unroll
        for (int i = 0; i < 3; i++) {
            int idx = tid + i * 256;      // 0..767
            int n = idx >> 2, seg = idx & 3;
            uint32_t d = (uint32_t)(n * QP + seg * 16);
            cp16(sb + OFF_W(buf, 0) + d, wth + (size_t)n * CC + k0 + seg * 8);
            cp16(sb + OFF_W(buf, 1) + d, wtl + (size_t)n * CC + k0 + seg * 8);
        }
    };

    // ldmatrix lane addressing
    const uint32_t a_off = (uint32_t)((wr * 16 + (lane & 15)) * QP +
                                      ((lane >> 4) & 1) * 16);
    const int b_row  = (lane & 7) + ((lane >> 4) & 1) * 8;
    const int b_sel  = (lane >> 3) & 1;
    const uint32_t b_off = (uint32_t)((wc * 96 + b_row) * QP + b_sel * 16);

    // prologue
    ldgA(0); stsA(0);
    cpW(0, 0); CP_COMMIT();
    ldgA(32);

    for (int kc = 0; kc < 32; kc++) {
        const int buf = kc & 1;
        if (kc + 1 < 32) cpW(buf ^ 1, (kc + 1) * 32);
        CP_COMMIT();
        CP_WAIT1();
        __syncthreads();

        const uint32_t ah_b = sb + OFF_A(buf, 0) + a_off;
        const uint32_t al_b = sb + OFF_A(buf, 1) + a_off;
        const uint32_t bh_b = sb + OFF_W(buf, 0) + b_off;
        const uint32_t bl_b = sb + OFF_W(buf, 1) + b_off;
#pragma unroll
        for (int ks = 0; ks < 2; ks++) {
            uint32_t ah[4], al[4];
            ldsm4(ah, ah_b + ks * 32);
            ldsm4(al, al_b + ks * 32);
#pragma unroll
            for (int j = 0; j < 6; j++) {
                uint32_t bh[4], bl[4];
                ldsm4(bh, bh_b + j * 16 * QP + ks * 32);
                ldsm4(bl, bl_b + j * 16 * QP + ks * 32);
                mma16816(acc[2 * j],     ah, bh[0], bh[1]);
                mma16816(acc[2 * j + 1], ah, bh[2], bh[3]);
                mma16816(acc[2 * j],     al, bh[0], bh[1]);
                mma16816(acc[2 * j + 1], al, bh[2], bh[3]);
                mma16816(acc[2 * j],     ah, bl[0], bl[1]);
                mma16816(acc[2 * j + 1], ah, bl[2], bl[3]);
            }
        }

        if (kc + 1 < 32) {
            __syncthreads();              // MMA reads of buf^1 done (prev iter)
            stsA(buf ^ 1);
            if (kc + 2 < 32) ldgA((kc + 2) * 32);
        }
    }
    __syncthreads();

    // ---- epilogue ----
    __nv_bfloat16* qh = (__nv_bfloat16*)g_qhi4;
    __nv_bfloat16* ql = (__nv_bfloat16*)g_qlo4;
    __nv_bfloat16* kh = (__nv_bfloat16*)g_khi4;
    __nv_bfloat16* kl = (__nv_bfloat16*)g_klo4;
    float* vbuf = (float*)smem;           // [64][65] fp32 (reuses gemm smem)
    const int fr = lane >> 2, fc = (lane & 3) * 2;

#pragma unroll
    for (int j = 0; j < 12; j++) {
        const int c = wc * 96 + j * 8 + fc;
        const int r = row0 + wr * 16 + fr;
        const float* a = acc[j];
        if (c < 128) {
            const bool isq = (c < 64);
            const float sc = isq ? SM_SCALE_LOG2E : 1.0f;
            __nv_bfloat16* oh = isq ? qh : kh;
            __nv_bfloat16* ol = isq ? ql : kl;
            const int cc = c & 63;
#pragma unroll
            for (int rr = 0; rr < 2; rr++) {
                float v0 = a[2 * rr] * sc, v1 = a[2 * rr + 1] * sc;
                float h0 = bf16rt(v0), h1 = bf16rt(v1);
                size_t o = (size_t)(r + rr * 8) * HH + cc;
                *(uint32_t*)&oh[o] = packbf2(h0, h1);
                *(uint32_t*)&ol[o] = packbf2(v0 - h0, v1 - h1);
            }
        } else {
            const int ch = c - 128;
            const int rl = r - row0;
            vbuf[rl * 65 + ch]           = a[0];
            vbuf[rl * 65 + ch + 1]       = a[1];
            vbuf[(rl + 8) * 65 + ch]     = a[2];
            vbuf[(rl + 8) * 65 + ch + 1] = a[3];
        }
    }
    __syncthreads();

    // transposed vt store: [b][h][t] hi/lo
    {
        __nv_bfloat16* vth = (__nv_bfloat16*)g_vthi4;
        __nv_bfloat16* vtl = (__nv_bfloat16*)g_vtlo4;
        const int bidx = row0 >> 12;      // /4096
        const int t0   = row0 & 4095;
#pragma unroll
        for (int i = 0; i < 16; i++) {
            int idx = tid + i * 256;      // 0..4095
            int h = idx >> 6, tt = idx & 63;
            float v = vbuf[tt * 65 + h];
            float hb = bf16rt(v);
            size_t o = (size_t)(bidx * HH + h) * TT + t0 + tt;
            vth[o] = __float2bfloat16_rn(hb);
            vtl[o] = __float2bfloat16_rn(v - hb);
        }
    }
}

// ---------------------------------------------------------------------------
// zero accumulators
// ---------------------------------------------------------------------------
__global__ __launch_bounds__(256) void zero_acc()
{
    int i = blockIdx.x * 256 + threadIdx.x;
    ((float4*)g_oacc)[i] = make_float4(0.f, 0.f, 0.f, 0.f);
    if (i < MM / 4)
        ((float4*)g_lacc)[i] = make_float4(0.f, 0.f, 0.f, 0.f);
}

// ---------------------------------------------------------------------------
// mma.sync flash attention (unchanged from round 6: 296 CTAs, 2/SM)
// ---------------------------------------------------------------------------
#define UPITCH 144            // 72 bf16 per row
#define OFF_QHI 0
#define OFF_QLO 18432
#define OFF_ST  36864
#define ST_STRIDE 36864
#define ST_KHI 0
#define ST_KLO 9216
#define ST_VHI 18432
#define ST_VLO 27648
#define ATT_SMEM 110592
#define ATT_NCTA 296
#define UNITS_PER_B 1056
#define TOTAL_UNITS (BB * UNITS_PER_B)

__device__ __forceinline__ void decode_unit(int u, int& b, int& qt, int& kc) {
    b = u / UNITS_PER_B;
    int r = u - b * UNITS_PER_B;
    int q = (int)((sqrtf(4.f * (float)r + 1.f) - 1.f) * 0.5f);
    while ((q + 1) * (q + 2) <= r) q++;
    while (q * (q + 1) > r) q--;
    qt = q;
    kc = r - q * (q + 1);
}

__global__ __launch_bounds__(256, 2) void attn_kernel()
{
    extern __shared__ char smem[];
    const uint32_t sb = smem_u32(smem);

    const int tid  = threadIdx.x;
    const int wid  = tid >> 5;
    const int lane = tid & 31;

    const __nv_bfloat16* gqh = (const __nv_bfloat16*)g_qhi4;
    const __nv_bfloat16* gql = (const __nv_bfloat16*)g_qlo4;
    const __nv_bfloat16* gkh = (const __nv_bfloat16*)g_khi4;
    const __nv_bfloat16* gkl = (const __nv_bfloat16*)g_klo4;
    const __nv_bfloat16* gvh = (const __nv_bfloat16*)g_vthi4;
    const __nv_bfloat16* gvl = (const __nv_bfloat16*)g_vtlo4;

    const int u0 = (int)(((long long)TOTAL_UNITS * blockIdx.x) / ATT_NCTA);
    const int u1 = (int)(((long long)TOTAL_UNITS * (blockIdx.x + 1)) / ATT_NCTA);

    const int a_row  = wid * 16 + (lane & 15);
    const int a_csel = (lane >> 4) & 1;
    const uint32_t qh_base = sb + OFF_QHI + a_row * UPITCH + a_csel * 16;
    const uint32_t ql_base = sb + OFF_QLO + a_row * UPITCH + a_csel * 16;
    const int b_key  = (lane & 7) + ((lane >> 4) & 1) * 8;
    const int b_hsel = (lane >> 3) & 1;
    const int v_h    = (lane & 7) + ((lane >> 4) & 1) * 8;
    const int v_ksel = (lane >> 3) & 1;

    auto prefetch = [&](int st, int b, int kc) {
        uint32_t so = sb + OFF_ST + st * ST_STRIDE;
        const __nv_bfloat16* kh = gkh + (size_t)(b * TT + kc * 64) * HH;
        const __nv_bfloat16* kl = gkl + (size_t)(b * TT + kc * 64) * HH;
        const __nv_bfloat16* vh = gvh + (size_t)b * HH * TT + (size_t)kc * 64;
        const __nv_bfloat16* vl = gvl + (size_t)b * HH * TT + (size_t)kc * 64;
#pragma unroll
        for (int i = 0; i < 2; i++) {
            int idx = tid + i * 256;
            int r = idx >> 3, c = idx & 7;
            uint32_t d = r * UPITCH + c * 16;
            cp16(so + ST_KHI + d, kh + (size_t)r * HH + c * 8);
            cp16(so + ST_KLO + d, kl + (size_t)r * HH + c * 8);
            cp16(so + ST_VHI + d, vh + (size_t)r * TT + c * 8);
            cp16(so + ST_VLO + d, vl + (size_t)r * TT + c * 8);
        }
    };

    {
        int b, qt, kc;
        decode_unit(u0, b, qt, kc);
        prefetch(u0 & 1, b, kc);
        CP_COMMIT();
        if (u0 + 1 < u1) {
            decode_unit(u0 + 1, b, qt, kc);
            prefetch((u0 + 1) & 1, b, kc);
        }
        CP_COMMIT();
    }

    float of[8][4];
    float lsum0 = 0.f, lsum1 = 0.f;
    int cur_b = -1, cur_qt = -1;

    auto flush = [&](int cb, int cq) {
        float s0 = lsum0, s1 = lsum1;
#pragma unroll
        for (int d = 1; d < 4; d <<= 1) {
            s0 += __shfl_xor_sync(0xffffffffu, s0, d);
            s1 += __shfl_xor_sync(0xffffffffu, s1, d);
        }
        int qb = cb * TT + cq * 128;
        int row0 = qb + wid * 16 + (lane >> 2);
        if ((lane & 3) == 0) {
            atomicAdd(&g_lacc[row0], s0);
            atomicAdd(&g_lacc[row0 + 8], s1);
        }
#pragma unroll
        for (int n8 = 0; n8 < 8; n8++) {
            int col = n8 * 8 + (lane & 3) * 2;
            atomicAdd(&g_oacc[(size_t)row0 * HH + col],           of[n8][0]);
            atomicAdd(&g_oacc[(size_t)row0 * HH + col + 1],       of[n8][1]);
            atomicAdd(&g_oacc[(size_t)(row0 + 8) * HH + col],     of[n8][2]);
            atomicAdd(&g_oacc[(size_t)(row0 + 8) * HH + col + 1], of[n8][3]);
        }
    };

    for (int u = u0; u < u1; u++) {
        int b, qt, kc;
        decode_unit(u, b, qt, kc);

        CP_WAIT1();
        __syncthreads();

        if (b != cur_b || qt != cur_qt) {
            if (cur_qt >= 0) flush(cur_b, cur_qt);
#pragma unroll
            for (int i = 0; i < 8; i++)
#pragma unroll
                for (int j = 0; j < 4; j++) of[i][j] = 0.f;
            lsum0 = lsum1 = 0.f;
            const __nv_bfloat16* qhp = gqh + (size_t)(b * TT + qt * 128) * HH;
            const __nv_bfloat16* qlp = gql + (size_t)(b * TT + qt * 128) * HH;
#pragma unroll
            for (int i = 0; i < 4; i++) {
                int idx = tid + i * 256;
                int r = idx >> 3, c = idx & 7;
                *(uint4*)(smem + OFF_QHI + r * UPITCH + c * 16) =
                    *(const uint4*)(qhp + (size_t)r * HH + c * 8);
                *(uint4*)(smem + OFF_QLO + r * UPITCH + c * 16) =
                    *(const uint4*)(qlp + (size_t)r * HH + c * 8);
            }
            __syncthreads();
            cur_b = b; cur_qt = qt;
        }

        const uint32_t so = sb + OFF_ST + (u & 1) * ST_STRIDE;

        // ---- S = Q K^T (Q fragments loaded per ks) ----
        float sf[8][4];
#pragma unroll
        for (int i = 0; i < 8; i++)
#pragma unroll
            for (int j = 0; j < 4; j++) sf[i][j] = 0.f;

#pragma unroll
        for (int ks = 0; ks < 4; ks++) {
            uint32_t qah[4], qal[4];
            ldsm4(qah, qh_base + ks * 32);
            ldsm4(qal, ql_base + ks * 32);
#pragma unroll
            for (int g = 0; g < 4; g++) {
                uint32_t bh[4], bl[4];
                uint32_t ka = so + (16 * g + b_key) * UPITCH + ks * 32 + b_hsel * 16;
                ldsm4(bh, ka + ST_KHI);
                ldsm4(bl, ka + ST_KLO);
                mma16816(sf[2 * g],     qah, bh[0], bh[1]);
                mma16816(sf[2 * g + 1], qah, bh[2], bh[3]);
                mma16816(sf[2 * g],     qal, bh[0], bh[1]);
                mma16816(sf[2 * g + 1], qal, bh[2], bh[3]);
                mma16816(sf[2 * g],     qah, bl[0], bl[1]);
                mma16816(sf[2 * g + 1], qah, bl[2], bl[3]);
            }
        }

        // ---- fused softmax + PV per 16-column P chunk ----
        const bool needmask = (kc >= 2 * qt);
        const int qrow0 = qt * 128 + wid * 16 + (lane >> 2);
        const int keyb  = kc * 64 + (lane & 3) * 2;
#pragma unroll
        for (int pks = 0; pks < 4; pks++) {
            uint32_t pah[4], pal[4];
#pragma unroll
            for (int h = 0; h < 2; h++) {
                const int n8 = 2 * pks + h;
                int k0 = keyb + n8 * 8;
                float p0 = fast_ex2(sf[n8][0]);
                float p1 = fast_ex2(sf[n8][1]);
                float p2 = fast_ex2(sf[n8][2]);
                float p3 = fast_ex2(sf[n8][3]);
                if (needmask) {
                    if (k0     > qrow0)     p0 = 0.f;
                    if (k0 + 1 > qrow0)     p1 = 0.f;
                    if (k0     > qrow0 + 8) p2 = 0.f;
                    if (k0 + 1 > qrow0 + 8) p3 = 0.f;
                }
                lsum0 += p0 + p1;
                lsum1 += p2 + p3;
                float h0 = bf16rt(p0), h1 = bf16rt(p1);
                float h2 = bf16rt(p2), h3 = bf16rt(p3);
                pah[2 * h]     = packbf2(h0, h1);
                pah[2 * h + 1] = packbf2(h2, h3);
                pal[2 * h]     = packbf2(p0 - h0, p1 - h1);
                pal[2 * h + 1] = packbf2(p2 - h2, p3 - h3);
            }
#pragma unroll
            for (int g = 0; g < 4; g++) {
                uint32_t vh[4], vl[4];
                uint32_t va = so + (16 * g + v_h) * UPITCH + pks * 32 + v_ksel * 16;
                ldsm4(vh, va + ST_VHI);
                ldsm4(vl, va + ST_VLO);
                mma16816(of[2 * g],     pah, vh[0], vh[1]);
                mma16816(of[2 * g + 1], pah, vh[2], vh[3]);
                mma16816(of[2 * g],     pal, vh[0], vh[1]);
                mma16816(of[2 * g + 1], pal, vh[2], vh[3]);
                mma16816(of[2 * g],     pah, vl[0], vl[1]);
                mma16816(of[2 * g + 1], pah, vl[2], vl[3]);
            }
        }

        __syncthreads();
        if (u + 2 < u1) {
            int nb, nqt, nkc;
            decode_unit(u + 2, nb, nqt, nkc);
            prefetch(u & 1, nb, nkc);
        }
        CP_COMMIT();
    }

    flush(cur_b, cur_qt);
}

// ---------------------------------------------------------------------------
// finalize: out = O_acc / l
// ---------------------------------------------------------------------------
__global__ __launch_bounds__(256) void finalize(float* __restrict__ out)
{
    int i = blockIdx.x * 256 + threadIdx.x;
    float4 o = ((const float4*)g_oacc)[i];
    float inv = 1.0f / g_lacc[i >> 4];
    o.x *= inv; o.y *= inv; o.z *= inv; o.w *= inv;
    ((float4*)out)[i] = o;
}

// ---------------------------------------------------------------------------
extern "C" void kernel_launch(void* const* d_in, const int* in_sizes, int n_in,
                              void* d_out, int out_size)
{
    const float* x  = (const float*)d_in[0];
    const float* Wq = (const float*)d_in[1];
    const float* Wk = (const float*)d_in[2];
    const float* Wv = (const float*)d_in[3];
    float* out = (float*)d_out;

    cudaFuncSetAttribute(qkv3_kernel,
                         cudaFuncAttributeMaxDynamicSharedMemorySize, QKV3_SMEM);
    cudaFuncSetAttribute(attn_kernel,
                         cudaFuncAttributeMaxDynamicSharedMemorySize, ATT_SMEM);

    dim3 pw_grid(16, 3);
    prep_w<<<pw_grid, 256>>>(Wq, Wk, Wv);

    qkv3_kernel<<<MM / QKV_ROWS, 256, QKV3_SMEM>>>(x);

    zero_acc<<<MM * HH / 4 / 256, 256>>>();

    attn_kernel<<<ATT_NCTA, 256, ATT_SMEM>>>();

    finalize<<<MM * HH / 4 / 256, 256>>>(out);
}

// round 8
// speedup vs baseline: 1.3917x; 1.3917x over previous
#include <cuda_runtime.h>
#include <cuda_bf16.h>
#include <cstdint>

// Problem constants
#define BB 4
#define TT 4096
#define CC 1024
#define HH 64
#define MM (BB * TT)          // 16384 rows

#define SM_SCALE_LOG2E (0.03125f * 1.4426950408889634f)

// ---------------------------------------------------------------------------
// Global scratch
// q,k: plain bf16 (softmax damps their rounding error).
// v: bf16 hi/lo split (linear error path -> full precision kept).
// ---------------------------------------------------------------------------
__device__ uint4  g_qbf4 [MM * HH * 2 / 16];  // bf16 [m][64]
__device__ uint4  g_kbf4 [MM * HH * 2 / 16];
__device__ uint4  g_vthi4[MM * HH * 2 / 16];  // bf16 [b][h][t]
__device__ uint4  g_vtlo4[MM * HH * 2 / 16];
__device__ uint4  g_wqk4 [128 * CC * 2 / 16]; // bf16 Wt rows 0-63 q, 64-127 k
__device__ uint4  g_wvh4 [64 * CC * 2 / 16];  // bf16 Wv^T hi
__device__ uint4  g_wvl4 [64 * CC * 2 / 16];  // bf16 Wv^T lo
__device__ float  g_oacc[MM * HH];            // fp32 un-normalized O
__device__ float  g_lacc[MM];                 // fp32 row sums

__device__ __forceinline__ float fast_ex2(float x) {
    float y;
    asm("ex2.approx.ftz.f32 %0, %1;" : "=f"(y) : "f"(x));
    return y;
}
__device__ __forceinline__ uint32_t smem_u32(const void* p) {
    uint32_t a;
    asm("{ .reg .u64 t; cvta.to.shared.u64 t, %1; cvt.u32.u64 %0, t; }"
        : "=r"(a) : "l"(p));
    return a;
}
__device__ __forceinline__ void ldsm4(uint32_t* r, uint32_t addr) {
    asm volatile("ldmatrix.sync.aligned.m8n8.x4.shared.b16 {%0,%1,%2,%3}, [%4];"
                 : "=r"(r[0]), "=r"(r[1]), "=r"(r[2]), "=r"(r[3]) : "r"(addr));
}
__device__ __forceinline__ void mma16816(float* d, const uint32_t* a,
                                         uint32_t b0, uint32_t b1) {
    asm volatile("mma.sync.aligned.m16n8k16.row.col.f32.bf16.bf16.f32 "
                 "{%0,%1,%2,%3}, {%4,%5,%6,%7}, {%8,%9}, {%0,%1,%2,%3};"
                 : "+f"(d[0]), "+f"(d[1]), "+f"(d[2]), "+f"(d[3])
                 : "r"(a[0]), "r"(a[1]), "r"(a[2]), "r"(a[3]), "r"(b0), "r"(b1));
}
__device__ __forceinline__ void cp16(uint32_t dst, const void* src) {
    asm volatile("cp.async.cg.shared.global [%0], [%1], 16;"
                 :: "r"(dst), "l"(src));
}
#define CP_COMMIT() asm volatile("cp.async.commit_group;" ::: "memory")
#define CP_WAIT1()  asm volatile("cp.async.wait_group 1;" ::: "memory")
__device__ __forceinline__ uint32_t packbf2(float lo, float hi) {
    uint32_t r;
    asm("cvt.rn.bf16x2.f32 %0, %1, %2;" : "=r"(r) : "f"(hi), "f"(lo));
    return r;
}
__device__ __forceinline__ float bf16rt(float x) {
    return __bfloat162float(__float2bfloat16_rn(x));
}

// ---------------------------------------------------------------------------
// prep_w: transpose W. q/k -> plain bf16 rows of g_wqk; v -> hi/lo split.
// ---------------------------------------------------------------------------
__global__ __launch_bounds__(256) void prep_w(
    const float* __restrict__ Wq, const float* __restrict__ Wk,
    const float* __restrict__ Wv)
{
    __shared__ float ws[64][65];
    const int kc  = blockIdx.x;          // 0..15 (64-k slabs)
    const int mat = blockIdx.y;
    const float* __restrict__ W = (mat == 0) ? Wq : (mat == 1) ? Wk : Wv;
    const int t = threadIdx.x;

#pragma unroll
    for (int i = 0; i < 16; i++) {
        int idx = t + i * 256;
        int kk = idx >> 6, h = idx & 63;
        ws[kk][h] = W[(size_t)(kc * 64 + kk) * HH + h];
    }
    __syncthreads();

    if (mat < 2) {
        __nv_bfloat16* wqk = (__nv_bfloat16*)g_wqk4;
#pragma unroll
        for (int i = 0; i < 16; i++) {
            int idx = t + i * 256;
            int h = idx >> 6, kk = idx & 63;
            wqk[(size_t)(mat * 64 + h) * CC + kc * 64 + kk] =
                __float2bfloat16_rn(ws[kk][h]);
        }
    } else {
        __nv_bfloat16* wvh = (__nv_bfloat16*)g_wvh4;
        __nv_bfloat16* wvl = (__nv_bfloat16*)g_wvl4;
#pragma unroll
        for (int i = 0; i < 16; i++) {
            int idx = t + i * 256;
            int h = idx >> 6, kk = idx & 63;
            float v = ws[kk][h];
            float hb = bf16rt(v);
            size_t o = (size_t)h * CC + kc * 64 + kk;
            wvh[o] = __float2bfloat16_rn(hb);
            wvl[o] = __float2bfloat16_rn(v - hb);
        }
    }
}

// ---------------------------------------------------------------------------
// qkv3: fused projection [16384x1024]@[1024x192]. 64-row tiles, 256 CTAs,
// 2 CTAs/SM. Warps 4r x 2c. Balanced mixed-precision columns per warp:
//   8 n8-groups of q-or-k (1-pass, wc selects q or k) +
//   4 n8-groups of v (3-pass split-bf16, wc selects half)  = 20 MMA/ks.
// ---------------------------------------------------------------------------
#define QP 80                 // row pitch in bytes (40 bf16)
#define QKV_ROWS 64
#define AS_BYTES (QKV_ROWS * QP)            // 5120
#define OFF_A(buf, sp) ((((buf) * 2 + (sp)) * AS_BYTES))
#define WQK_BYTES (128 * QP)                // 10240
#define WV_BYTES  (64 * QP)                 // 5120
#define W_STAGE   (WQK_BYTES + 2 * WV_BYTES)  // 20480
#define OFF_WQK(buf) (4 * AS_BYTES + (buf) * W_STAGE)
#define OFF_WVH(buf) (OFF_WQK(buf) + WQK_BYTES)
#define OFF_WVL(buf) (OFF_WVH(buf) + WV_BYTES)
#define QKV3_SMEM (4 * AS_BYTES + 2 * W_STAGE)   // 61440

__global__ __launch_bounds__(256, 2) void qkv3_kernel(const float* __restrict__ x)
{
    extern __shared__ char smem[];
    const uint32_t sb = smem_u32(smem);
    const int tid  = threadIdx.x;
    const int wid  = tid >> 5;
    const int lane = tid & 31;
    const int wr   = wid >> 1;            // 0..3: rows wr*16
    const int wc   = wid & 1;             // 0..1: q-or-k / v-half select
    const int row0 = blockIdx.x * QKV_ROWS;

    const __nv_bfloat16* wqk = (const __nv_bfloat16*)g_wqk4;
    const __nv_bfloat16* wvh = (const __nv_bfloat16*)g_wvh4;
    const __nv_bfloat16* wvl = (const __nv_bfloat16*)g_wvl4;

    float acc[12][4];
#pragma unroll
    for (int j = 0; j < 12; j++)
#pragma unroll
        for (int e = 0; e < 4; e++) acc[j][e] = 0.f;

    // A staging: 64 rows x 32 k fp32 per chunk; x -> bf16 hi/lo in-register
    const int akq = tid & 7, ar = tid >> 3;        // ar 0..31
    float4 areg[2];
    auto ldgA = [&](int k0) {
#pragma unroll
        for (int it = 0; it < 2; it++)
            areg[it] = *(const float4*)&x[(size_t)(row0 + ar + 32 * it) * CC +
                                          k0 + akq * 4];
    };
    auto stsA = [&](int buf) {
#pragma unroll
        for (int it = 0; it < 2; it++) {
            float4 v = areg[it];
            float hx = bf16rt(v.x), hy = bf16rt(v.y);
            float hz = bf16rt(v.z), hw = bf16rt(v.w);
            uint32_t off = (uint32_t)((ar + 32 * it) * QP + akq * 8);
            *(uint2*)(smem + OFF_A(buf, 0) + off) =
                make_uint2(packbf2(hx, hy), packbf2(hz, hw));
            *(uint2*)(smem + OFF_A(buf, 1) + off) =
                make_uint2(packbf2(v.x - hx, v.y - hy),
                           packbf2(v.z - hz, v.w - hw));
        }
    };
    auto cpW = [&](int buf, int k0) {
#pragma unroll
        for (int i = 0; i < 2; i++) {
            int idx = tid + i * 256;      // 0..511
            int n = idx >> 2, seg = idx & 3;
            cp16(sb + OFF_WQK(buf) + (uint32_t)(n * QP + seg * 16),
                 wqk + (size_t)n * CC + k0 + seg * 8);
        }
        {
            int n = tid >> 2, seg = tid & 3;   // 64 rows x 4 segs = 256
            uint32_t d = (uint32_t)(n * QP + seg * 16);
            cp16(sb + OFF_WVH(buf) + d, wvh + (size_t)n * CC + k0 + seg * 8);
            cp16(sb + OFF_WVL(buf) + d, wvl + (size_t)n * CC + k0 + seg * 8);
        }
    };

    // ldmatrix lane addressing
    const uint32_t a_off = (uint32_t)((wr * 16 + (lane & 15)) * QP +
                                      ((lane >> 4) & 1) * 16);
    const int b_row = (lane & 7) + ((lane >> 4) & 1) * 8;
    const int b_sel = (lane >> 3) & 1;

    // prologue
    ldgA(0); stsA(0);
    cpW(0, 0); CP_COMMIT();
    ldgA(32);

    for (int kc = 0; kc < 32; kc++) {
        const int buf = kc & 1;
        if (kc + 1 < 32) cpW(buf ^ 1, (kc + 1) * 32);
        CP_COMMIT();
        CP_WAIT1();
        __syncthreads();

        const uint32_t ah_b  = sb + OFF_A(buf, 0) + a_off;
        const uint32_t al_b  = sb + OFF_A(buf, 1) + a_off;
        const uint32_t bqk_b = sb + OFF_WQK(buf) +
                               (uint32_t)((wc * 64 + b_row) * QP + b_sel * 16);
        const uint32_t bvh_b = sb + OFF_WVH(buf) +
                               (uint32_t)((wc * 32 + b_row) * QP + b_sel * 16);
        const uint32_t bvl_b = sb + OFF_WVL(buf) +
                               (uint32_t)((wc * 32 + b_row) * QP + b_sel * 16);
#pragma unroll
        for (int ks = 0; ks < 2; ks++) {
            uint32_t ah[4], al[4];
            ldsm4(ah, ah_b + ks * 32);
            ldsm4(al, al_b + ks * 32);
#pragma unroll
            for (int g = 0; g < 4; g++) {     // q-or-k: 1-pass
                uint32_t bh[4];
                ldsm4(bh, bqk_b + g * 16 * QP + ks * 32);
                mma16816(acc[2 * g],     ah, bh[0], bh[1]);
                mma16816(acc[2 * g + 1], ah, bh[2], bh[3]);
            }
#pragma unroll
            for (int g = 0; g < 2; g++) {     // v: 3-pass
                uint32_t bh[4], bl[4];
                ldsm4(bh, bvh_b + g * 16 * QP + ks * 32);
                ldsm4(bl, bvl_b + g * 16 * QP + ks * 32);
                mma16816(acc[8 + 2 * g], ah, bh[0], bh[1]);
                mma16816(acc[9 + 2 * g], ah, bh[2], bh[3]);
                mma16816(acc[8 + 2 * g], al, bh[0], bh[1]);
                mma16816(acc[9 + 2 * g], al, bh[2], bh[3]);
                mma16816(acc[8 + 2 * g], ah, bl[0], bl[1]);
                mma16816(acc[9 + 2 * g], ah, bl[2], bl[3]);
            }
        }

        if (kc + 1 < 32) {
            __syncthreads();              // MMA reads of buf^1 done (prev iter)
            stsA(buf ^ 1);
            if (kc + 2 < 32) ldgA((kc + 2) * 32);
        }
    }
    __syncthreads();

    // ---- epilogue ----
    __nv_bfloat16* qb = (__nv_bfloat16*)g_qbf4;
    __nv_bfloat16* kb = (__nv_bfloat16*)g_kbf4;
    float* vbuf = (float*)smem;           // [64][65] fp32 (reuses gemm smem)
    const int fr = lane >> 2, fc = (lane & 3) * 2;
    const int r = row0 + wr * 16 + fr;

    // q/k: plain bf16 store (wc=0 -> q cols 0-63 scaled; wc=1 -> k)
    {
        __nv_bfloat16* dst = wc ? kb : qb;
        const float sc = wc ? 1.0f : SM_SCALE_LOG2E;
#pragma unroll
        for (int j = 0; j < 8; j++) {
            const int cc = j * 8 + fc;
            const float* a = acc[j];
#pragma unroll
            for (int rr = 0; rr < 2; rr++) {
                size_t o = (size_t)(r + rr * 8) * HH + cc;
                *(uint32_t*)&dst[o] = packbf2(a[2 * rr] * sc, a[2 * rr + 1] * sc);
            }
        }
    }
    // v: stage fp32 into vbuf for transpose
#pragma unroll
    for (int j = 0; j < 4; j++) {
        const int ch = wc * 32 + j * 8 + fc;
        const int rl = r - row0;
        const float* a = acc[8 + j];
        vbuf[rl * 65 + ch]           = a[0];
        vbuf[rl * 65 + ch + 1]       = a[1];
        vbuf[(rl + 8) * 65 + ch]     = a[2];
        vbuf[(rl + 8) * 65 + ch + 1] = a[3];
    }
    __syncthreads();

    // transposed vt store: [b][h][t] hi/lo
    {
        __nv_bfloat16* vth = (__nv_bfloat16*)g_vthi4;
        __nv_bfloat16* vtl = (__nv_bfloat16*)g_vtlo4;
        const int bidx = row0 >> 12;      // /4096
        const int t0   = row0 & 4095;
#pragma unroll
        for (int i = 0; i < 16; i++) {
            int idx = tid + i * 256;      // 0..4095
            int h = idx >> 6, tt = idx & 63;
            float v = vbuf[tt * 65 + h];
            float hb = bf16rt(v);
            size_t o = (size_t)(bidx * HH + h) * TT + t0 + tt;
            vth[o] = __float2bfloat16_rn(hb);
            vtl[o] = __float2bfloat16_rn(v - hb);
        }
    }
}

// ---------------------------------------------------------------------------
// zero accumulators
// ---------------------------------------------------------------------------
__global__ __launch_bounds__(256) void zero_acc()
{
    int i = blockIdx.x * 256 + threadIdx.x;
    ((float4*)g_oacc)[i] = make_float4(0.f, 0.f, 0.f, 0.f);
    if (i < MM / 4)
        ((float4*)g_lacc)[i] = make_float4(0.f, 0.f, 0.f, 0.f);
}

// ---------------------------------------------------------------------------
// mma.sync flash attention. S = QK^T single-pass bf16 (softmax damps error);
// PV keeps split-bf16 3-pass. 296 persistent CTAs (2/SM).
// smem: Q [128][72]bf16 + 2 stages of {K, Vt hi, Vt lo [64][72]}
// ---------------------------------------------------------------------------
#define UPITCH 144            // 72 bf16 per row
#define OFF_QHI 0
#define OFF_ST  18432
#define ST_STRIDE 27648
#define ST_KHI 0
#define ST_VHI 9216
#define ST_VLO 18432
#define ATT_SMEM (18432 + 2 * 27648)   // 73728
#define ATT_NCTA 296
#define UNITS_PER_B 1056
#define TOTAL_UNITS (BB * UNITS_PER_B)

__device__ __forceinline__ void decode_unit(int u, int& b, int& qt, int& kc) {
    b = u / UNITS_PER_B;
    int r = u - b * UNITS_PER_B;
    int q = (int)((sqrtf(4.f * (float)r + 1.f) - 1.f) * 0.5f);
    while ((q + 1) * (q + 2) <= r) q++;
    while (q * (q + 1) > r) q--;
    qt = q;
    kc = r - q * (q + 1);
}

__global__ __launch_bounds__(256, 2) void attn_kernel()
{
    extern __shared__ char smem[];
    const uint32_t sb = smem_u32(smem);

    const int tid  = threadIdx.x;
    const int wid  = tid >> 5;
    const int lane = tid & 31;

    const __nv_bfloat16* gq  = (const __nv_bfloat16*)g_qbf4;
    const __nv_bfloat16* gk  = (const __nv_bfloat16*)g_kbf4;
    const __nv_bfloat16* gvh = (const __nv_bfloat16*)g_vthi4;
    const __nv_bfloat16* gvl = (const __nv_bfloat16*)g_vtlo4;

    const int u0 = (int)(((long long)TOTAL_UNITS * blockIdx.x) / ATT_NCTA);
    const int u1 = (int)(((long long)TOTAL_UNITS * (blockIdx.x + 1)) / ATT_NCTA);

    const int a_row  = wid * 16 + (lane & 15);
    const int a_csel = (lane >> 4) & 1;
    const uint32_t q_base = sb + OFF_QHI + a_row * UPITCH + a_csel * 16;
    const int b_key  = (lane & 7) + ((lane >> 4) & 1) * 8;
    const int b_hsel = (lane >> 3) & 1;
    const int v_h    = (lane & 7) + ((lane >> 4) & 1) * 8;
    const int v_ksel = (lane >> 3) & 1;

    auto prefetch = [&](int st, int b, int kc) {
        uint32_t so = sb + OFF_ST + st * ST_STRIDE;
        const __nv_bfloat16* kp = gk  + (size_t)(b * TT + kc * 64) * HH;
        const __nv_bfloat16* vh = gvh + (size_t)b * HH * TT + (size_t)kc * 64;
        const __nv_bfloat16* vl = gvl + (size_t)b * HH * TT + (size_t)kc * 64;
#pragma unroll
        for (int i = 0; i < 2; i++) {
            int idx = tid + i * 256;
            int r = idx >> 3, c = idx & 7;
            uint32_t d = r * UPITCH + c * 16;
            cp16(so + ST_KHI + d, kp + (size_t)r * HH + c * 8);
            cp16(so + ST_VHI + d, vh + (size_t)r * TT + c * 8);
            cp16(so + ST_VLO + d, vl + (size_t)r * TT + c * 8);
        }
    };

    {
        int b, qt, kc;
        decode_unit(u0, b, qt, kc);
        prefetch(u0 & 1, b, kc);
        CP_COMMIT();
        if (u0 + 1 < u1) {
            decode_unit(u0 + 1, b, qt, kc);
            prefetch((u0 + 1) & 1, b, kc);
        }
        CP_COMMIT();
    }

    float of[8][4];
    float lsum0 = 0.f, lsum1 = 0.f;
    int cur_b = -1, cur_qt = -1;

    auto flush = [&](int cb, int cq) {
        float s0 = lsum0, s1 = lsum1;
#pragma unroll
        for (int d = 1; d < 4; d <<= 1) {
            s0 += __shfl_xor_sync(0xffffffffu, s0, d);
            s1 += __shfl_xor_sync(0xffffffffu, s1, d);
        }
        int qb = cb * TT + cq * 128;
        int row0 = qb + wid * 16 + (lane >> 2);
        if ((lane & 3) == 0) {
            atomicAdd(&g_lacc[row0], s0);
            atomicAdd(&g_lacc[row0 + 8], s1);
        }
#pragma unroll
        for (int n8 = 0; n8 < 8; n8++) {
            int col = n8 * 8 + (lane & 3) * 2;
            atomicAdd(&g_oacc[(size_t)row0 * HH + col],           of[n8][0]);
            atomicAdd(&g_oacc[(size_t)row0 * HH + col + 1],       of[n8][1]);
            atomicAdd(&g_oacc[(size_t)(row0 + 8) * HH + col],     of[n8][2]);
            atomicAdd(&g_oacc[(size_t)(row0 + 8) * HH + col + 1], of[n8][3]);
        }
    };

    for (int u = u0; u < u1; u++) {
        int b, qt, kc;
        decode_unit(u, b, qt, kc);

        CP_WAIT1();
        __syncthreads();

        if (b != cur_b || qt != cur_qt) {
            if (cur_qt >= 0) flush(cur_b, cur_qt);
#pragma unroll
            for (int i = 0; i < 8; i++)
#pragma unroll
                for (int j = 0; j < 4; j++) of[i][j] = 0.f;
            lsum0 = lsum1 = 0.f;
            const __nv_bfloat16* qp = gq + (size_t)(b * TT + qt * 128) * HH;
#pragma unroll
            for (int i = 0; i < 4; i++) {
                int idx = tid + i * 256;
                int r = idx >> 3, c = idx & 7;
                *(uint4*)(smem + OFF_QHI + r * UPITCH + c * 16) =
                    *(const uint4*)(qp + (size_t)r * HH + c * 8);
            }
            __syncthreads();
            cur_b = b; cur_qt = qt;
        }

        const uint32_t so = sb + OFF_ST + (u & 1) * ST_STRIDE;

        // ---- S = Q K^T (single bf16 pass) ----
        float sf[8][4];
#pragma unroll
        for (int i = 0; i < 8; i++)
#pragma unroll
            for (int j = 0; j < 4; j++) sf[i][j] = 0.f;

#pragma unroll
        for (int ks = 0; ks < 4; ks++) {
            uint32_t qa[4];
            ldsm4(qa, q_base + ks * 32);
#pragma unroll
            for (int g = 0; g < 4; g++) {
                uint32_t bh[4];
                ldsm4(bh, so + ST_KHI + (16 * g + b_key) * UPITCH +
                          ks * 32 + b_hsel * 16);
                mma16816(sf[2 * g],     qa, bh[0], bh[1]);
                mma16816(sf[2 * g + 1], qa, bh[2], bh[3]);
            }
        }

        // ---- fused softmax + PV per 16-column P chunk (P 3-pass) ----
        const bool needmask = (kc >= 2 * qt);
        const int qrow0 = qt * 128 + wid * 16 + (lane >> 2);
        const int keyb  = kc * 64 + (lane & 3) * 2;
#pragma unroll
        for (int pks = 0; pks < 4; pks++) {
            uint32_t pah[4], pal[4];
#pragma unroll
            for (int h = 0; h < 2; h++) {
                const int n8 = 2 * pks + h;
                int k0 = keyb + n8 * 8;
                float p0 = fast_ex2(sf[n8][0]);
                float p1 = fast_ex2(sf[n8][1]);
                float p2 = fast_ex2(sf[n8][2]);
                float p3 = fast_ex2(sf[n8][3]);
                if (needmask) {
                    if (k0     > qrow0)     p0 = 0.f;
                    if (k0 + 1 > qrow0)     p1 = 0.f;
                    if (k0     > qrow0 + 8) p2 = 0.f;
                    if (k0 + 1 > qrow0 + 8) p3 = 0.f;
                }
                lsum0 += p0 + p1;
                lsum1 += p2 + p3;
                float h0 = bf16rt(p0), h1 = bf16rt(p1);
                float h2 = bf16rt(p2), h3 = bf16rt(p3);
                pah[2 * h]     = packbf2(h0, h1);
                pah[2 * h + 1] = packbf2(h2, h3);
                pal[2 * h]     = packbf2(p0 - h0, p1 - h1);
                pal[2 * h + 1] = packbf2(p2 - h2, p3 - h3);
            }
#pragma unroll
            for (int g = 0; g < 4; g++) {
                uint32_t vh[4], vl[4];
                uint32_t va = so + (16 * g + v_h) * UPITCH + pks * 32 + v_ksel * 16;
                ldsm4(vh, va + ST_VHI);
                ldsm4(vl, va + ST_VLO);
                mma16816(of[2 * g],     pah, vh[0], vh[1]);
                mma16816(of[2 * g + 1], pah, vh[2], vh[3]);
                mma16816(of[2 * g],     pal, vh[0], vh[1]);
                mma16816(of[2 * g + 1], pal, vh[2], vh[3]);
                mma16816(of[2 * g],     pah, vl[0], vl[1]);
                mma16816(of[2 * g + 1], pah, vl[2], vl[3]);
            }
        }

        __syncthreads();
        if (u + 2 < u1) {
            int nb, nqt, nkc;
            decode_unit(u + 2, nb, nqt, nkc);
            prefetch(u & 1, nb, nkc);
        }
        CP_COMMIT();
    }

    flush(cur_b, cur_qt);
}

// ---------------------------------------------------------------------------
// finalize: out = O_acc / l
// ---------------------------------------------------------------------------
__global__ __launch_bounds__(256) void finalize(float* __restrict__ out)
{
    int i = blockIdx.x * 256 + threadIdx.x;
    float4 o = ((const float4*)g_oacc)[i];
    float inv = 1.0f / g_lacc[i >> 4];
    o.x *= inv; o.y *= inv; o.z *= inv; o.w *= inv;
    ((float4*)out)[i] = o;
}

// ---------------------------------------------------------------------------
extern "C" void kernel_launch(void* const* d_in, const int* in_sizes, int n_in,
                              void* d_out, int out_size)
{
    const float* x  = (const float*)d_in[0];
    const float* Wq = (const float*)d_in[1];
    const float* Wk = (const float*)d_in[2];
    const float* Wv = (const float*)d_in[3];
    float* out = (float*)d_out;

    cudaFuncSetAttribute(qkv3_kernel,
                         cudaFuncAttributeMaxDynamicSharedMemorySize, QKV3_SMEM);
    cudaFuncSetAttribute(attn_kernel,
                         cudaFuncAttributeMaxDynamicSharedMemorySize, ATT_SMEM);

    dim3 pw_grid(16, 3);
    prep_w<<<pw_grid, 256>>>(Wq, Wk, Wv);

    qkv3_kernel<<<MM / QKV_ROWS, 256, QKV3_SMEM>>>(x);

    zero_acc<<<MM * HH / 4 / 256, 256>>>();

    attn_kernel<<<ATT_NCTA, 256, ATT_SMEM>>>();

    finalize<<<MM * HH / 4 / 256, 256>>>(out);
}

// round 10
// speedup vs baseline: 1.8655x; 1.3404x over previous
#include <cuda_runtime.h>
#include <cuda_fp16.h>
#include <cstdint>

// Problem constants
#define BB 4
#define TT 4096
#define CC 1024
#define HH 64
#define MM (BB * TT)          // 16384 rows

#define SM_SCALE_LOG2E (0.03125f * 1.4426950408889634f)

// ---------------------------------------------------------------------------
// Global scratch — everything fp16 single-precision-pass.
// ---------------------------------------------------------------------------
__device__ uint4  g_q4 [MM * HH * 2 / 16];   // fp16 [m][64] (pre-scaled)
__device__ uint4  g_k4 [MM * HH * 2 / 16];   // fp16 [m][64]
__device__ uint4  g_vt4[MM * HH * 2 / 16];   // fp16 [b][h][t]
__device__ uint4  g_wt4[192 * CC * 2 / 16];  // fp16 Wt [n=192][k=1024]
__device__ float  g_oacc[MM * HH];           // fp32 un-normalized O
__device__ float  g_lacc[MM];                // fp32 row sums

__device__ __forceinline__ float fast_ex2(float x) {
    float y;
    asm("ex2.approx.ftz.f32 %0, %1;" : "=f"(y) : "f"(x));
    return y;
}
__device__ __forceinline__ uint32_t smem_u32(const void* p) {
    uint32_t a;
    asm("{ .reg .u64 t; cvta.to.shared.u64 t, %1; cvt.u32.u64 %0, t; }"
        : "=r"(a) : "l"(p));
    return a;
}
__device__ __forceinline__ void ldsm4(uint32_t* r, uint32_t addr) {
    asm volatile("ldmatrix.sync.aligned.m8n8.x4.shared.b16 {%0,%1,%2,%3}, [%4];"
                 : "=r"(r[0]), "=r"(r[1]), "=r"(r[2]), "=r"(r[3]) : "r"(addr));
}
__device__ __forceinline__ void mma16816(float* d, const uint32_t* a,
                                         uint32_t b0, uint32_t b1) {
    asm volatile("mma.sync.aligned.m16n8k16.row.col.f32.f16.f16.f32 "
                 "{%0,%1,%2,%3}, {%4,%5,%6,%7}, {%8,%9}, {%0,%1,%2,%3};"
                 : "+f"(d[0]), "+f"(d[1]), "+f"(d[2]), "+f"(d[3])
                 : "r"(a[0]), "r"(a[1]), "r"(a[2]), "r"(a[3]), "r"(b0), "r"(b1));
}
__device__ __forceinline__ void cp16(uint32_t dst, const void* src) {
    asm volatile("cp.async.cg.shared.global [%0], [%1], 16;"
                 :: "r"(dst), "l"(src));
}
#define CP_COMMIT() asm volatile("cp.async.commit_group;" ::: "memory")
#define CP_WAIT1()  asm volatile("cp.async.wait_group 1;" ::: "memory")
// pack {lower=lo, upper=hi} fp16x2
__device__ __forceinline__ uint32_t packf16(float lo, float hi) {
    uint32_t r;
    asm("cvt.rn.f16x2.f32 %0, %1, %2;" : "=r"(r) : "f"(hi), "f"(lo));
    return r;
}

// ---------------------------------------------------------------------------
// prep_w: transpose all W into fp16 Wt [n=mat*64+h][k=1024]
// ---------------------------------------------------------------------------
__global__ __launch_bounds__(256) void prep_w(
    const float* __restrict__ Wq, const float* __restrict__ Wk,
    const float* __restrict__ Wv)
{
    __shared__ float ws[64][65];
    const int kc  = blockIdx.x;          // 0..15 (64-k slabs)
    const int mat = blockIdx.y;
    const float* __restrict__ W = (mat == 0) ? Wq : (mat == 1) ? Wk : Wv;
    const int t = threadIdx.x;
    __half* wt = (__half*)g_wt4;

#pragma unroll
    for (int i = 0; i < 16; i++) {
        int idx = t + i * 256;
        int kk = idx >> 6, h = idx & 63;
        ws[kk][h] = W[(size_t)(kc * 64 + kk) * HH + h];
    }
    __syncthreads();
#pragma unroll
    for (int i = 0; i < 16; i++) {
        int idx = t + i * 256;
        int h = idx >> 6, kk = idx & 63;
        wt[(size_t)(mat * 64 + h) * CC + kc * 64 + kk] =
            __float2half_rn(ws[kk][h]);
    }
}

// ---------------------------------------------------------------------------
// qkv3: fused fp16 projection [16384x1024]@[1024x192]. 64-row tiles,
// 256 CTAs, 2 CTAs/SM. 8 warps = 4 rows x 2 col-halves (96 cols each),
// single-pass fp16 MMA. Epilogue: cols 0-63 q (scaled), 64-127 k,
// 128-191 v (transposed in-CTA to [b][h][t]).
// ---------------------------------------------------------------------------
#define QP 80                 // row pitch bytes (32 fp16 data + pad)
#define QKV_ROWS 64
#define AS_BYTES (QKV_ROWS * QP)            // 5120
#define WS_BYTES (192 * QP)                 // 15360
#define OFF_A(buf) ((buf) * AS_BYTES)
#define OFF_W(buf) (2 * AS_BYTES + (buf) * WS_BYTES)
#define QKV3_SMEM (2 * AS_BYTES + 2 * WS_BYTES)   // 40960

__global__ __launch_bounds__(256, 2) void qkv3_kernel(const float* __restrict__ x)
{
    extern __shared__ char smem[];
    const uint32_t sb = smem_u32(smem);
    const int tid  = threadIdx.x;
    const int wid  = tid >> 5;
    const int lane = tid & 31;
    const int wr   = wid >> 1;            // 0..3: rows wr*16
    const int wc   = wid & 1;             // 0..1: cols wc*96
    const int row0 = blockIdx.x * QKV_ROWS;

    const __half* wt = (const __half*)g_wt4;

    float acc[12][4];
#pragma unroll
    for (int j = 0; j < 12; j++)
#pragma unroll
        for (int e = 0; e < 4; e++) acc[j][e] = 0.f;

    // A staging: 64 rows x 32 k fp32 per chunk; x -> fp16 in-register
    const int akq = tid & 7, ar = tid >> 3;        // ar 0..31
    float4 areg[2];
    auto ldgA = [&](int k0) {
#pragma unroll
        for (int it = 0; it < 2; it++)
            areg[it] = *(const float4*)&x[(size_t)(row0 + ar + 32 * it) * CC +
                                          k0 + akq * 4];
    };
    auto stsA = [&](int buf) {
#pragma unroll
        for (int it = 0; it < 2; it++) {
            float4 v = areg[it];
            uint32_t off = (uint32_t)((ar + 32 * it) * QP + akq * 8);
            *(uint2*)(smem + OFF_A(buf) + off) =
                make_uint2(packf16(v.x, v.y), packf16(v.z, v.w));
        }
    };
    auto cpW = [&](int buf, int k0) {
#pragma unroll
        for (int i = 0; i < 3; i++) {
            int idx = tid + i * 256;      // 0..767
            int n = idx >> 2, seg = idx & 3;
            cp16(sb + OFF_W(buf) + (uint32_t)(n * QP + seg * 16),
                 wt + (size_t)n * CC + k0 + seg * 8);
        }
    };

    // ldmatrix lane addressing
    const uint32_t a_off = (uint32_t)((wr * 16 + (lane & 15)) * QP +
                                      ((lane >> 4) & 1) * 16);
    const int b_row = (lane & 7) + ((lane >> 4) & 1) * 8;
    const int b_sel = (lane >> 3) & 1;
    const uint32_t b_off = (uint32_t)((wc * 96 + b_row) * QP + b_sel * 16);

    // prologue
    ldgA(0); stsA(0);
    cpW(0, 0); CP_COMMIT();
    ldgA(32);

    for (int kc = 0; kc < 32; kc++) {
        const int buf = kc & 1;
        if (kc + 1 < 32) cpW(buf ^ 1, (kc + 1) * 32);
        CP_COMMIT();
        CP_WAIT1();
        __syncthreads();

        const uint32_t a_b = sb + OFF_A(buf) + a_off;
        const uint32_t b_b = sb + OFF_W(buf) + b_off;
#pragma unroll
        for (int ks = 0; ks < 2; ks++) {
            uint32_t ah[4];
            ldsm4(ah, a_b + ks * 32);
#pragma unroll
            for (int j = 0; j < 6; j++) {
                uint32_t bh[4];
                ldsm4(bh, b_b + j * 16 * QP + ks * 32);
                mma16816(acc[2 * j],     ah, bh[0], bh[1]);
                mma16816(acc[2 * j + 1], ah, bh[2], bh[3]);
            }
        }

        if (kc + 1 < 32) {
            __syncthreads();              // MMA reads of buf^1 done (prev iter)
            stsA(buf ^ 1);
            if (kc + 2 < 32) ldgA((kc + 2) * 32);
        }
    }
    __syncthreads();

    // ---- epilogue ----
    __half* qd = (__half*)g_q4;
    __half* kd = (__half*)g_k4;
    float* vbuf = (float*)smem;           // [64][65] fp32 (reuses gemm smem)
    const int fr = lane >> 2, fc = (lane & 3) * 2;
    const int r = row0 + wr * 16 + fr;

#pragma unroll
    for (int j = 0; j < 12; j++) {
        const int c = wc * 96 + j * 8 + fc;
        const float* a = acc[j];
        if (c < 128) {
            const bool isq = (c < 64);
            const float sc = isq ? SM_SCALE_LOG2E : 1.0f;
            __half* dst = isq ? qd : kd;
            const int cc = c & 63;
#pragma unroll
            for (int rr = 0; rr < 2; rr++) {
                size_t o = (size_t)(r + rr * 8) * HH + cc;
                *(uint32_t*)&dst[o] = packf16(a[2 * rr] * sc, a[2 * rr + 1] * sc);
            }
        } else {
            const int ch = c - 128;
            const int rl = r - row0;
            vbuf[rl * 65 + ch]           = a[0];
            vbuf[rl * 65 + ch + 1]       = a[1];
            vbuf[(rl + 8) * 65 + ch]     = a[2];
            vbuf[(rl + 8) * 65 + ch + 1] = a[3];
        }
    }
    __syncthreads();

    // transposed vt store: [b][h][t] fp16
    {
        __half* vt = (__half*)g_vt4;
        const int bidx = row0 >> 12;      // /4096
        const int t0   = row0 & 4095;
#pragma unroll
        for (int i = 0; i < 16; i++) {
            int idx = tid + i * 256;      // 0..4095
            int h = idx >> 6, tt = idx & 63;
            vt[(size_t)(bidx * HH + h) * TT + t0 + tt] =
                __float2half_rn(vbuf[tt * 65 + h]);
        }
    }
}

// ---------------------------------------------------------------------------
// zero accumulators
// ---------------------------------------------------------------------------
__global__ __launch_bounds__(256) void zero_acc()
{
    int i = blockIdx.x * 256 + threadIdx.x;
    ((float4*)g_oacc)[i] = make_float4(0.f, 0.f, 0.f, 0.f);
    if (i < MM / 4)
        ((float4*)g_lacc)[i] = make_float4(0.f, 0.f, 0.f, 0.f);
}

// ---------------------------------------------------------------------------
// fp16 mma.sync flash attention. S single-pass; P fp16 with consistent
// normalization (lsum sums the ROUNDED p, so P-quantization cancels through
// the final division); PV single-pass. 296 persistent CTAs (2/SM).
// smem: Q [128][72]fp16 + 2 stages of {K [64][72], Vt [64][72]}
// ---------------------------------------------------------------------------
#define UPITCH 144            // 72 fp16 per row
#define OFF_Q 0
#define OFF_ST  18432
#define ST_STRIDE 18432
#define ST_K 0
#define ST_V 9216
#define ATT_SMEM (18432 + 2 * 18432)   // 55296
#define ATT_NCTA 296
#define UNITS_PER_B 1056
#define TOTAL_UNITS (BB * UNITS_PER_B)

__device__ __forceinline__ void decode_unit(int u, int& b, int& qt, int& kc) {
    b = u / UNITS_PER_B;
    int r = u - b * UNITS_PER_B;
    int q = (int)((sqrtf(4.f * (float)r + 1.f) - 1.f) * 0.5f);
    while ((q + 1) * (q + 2) <= r) q++;
    while (q * (q + 1) > r) q--;
    qt = q;
    kc = r - q * (q + 1);
}

__global__ __launch_bounds__(256, 2) void attn_kernel()
{
    extern __shared__ char smem[];
    const uint32_t sb = smem_u32(smem);

    const int tid  = threadIdx.x;
    const int wid  = tid >> 5;
    const int lane = tid & 31;

    const __half* gq = (const __half*)g_q4;
    const __half* gk = (const __half*)g_k4;
    const __half* gv = (const __half*)g_vt4;

    const int u0 = (int)(((long long)TOTAL_UNITS * blockIdx.x) / ATT_NCTA);
    const int u1 = (int)(((long long)TOTAL_UNITS * (blockIdx.x + 1)) / ATT_NCTA);

    const int a_row  = wid * 16 + (lane & 15);
    const int a_csel = (lane >> 4) & 1;
    const uint32_t q_base = sb + OFF_Q + a_row * UPITCH + a_csel * 16;
    const int b_key  = (lane & 7) + ((lane >> 4) & 1) * 8;
    const int b_hsel = (lane >> 3) & 1;
    const int v_h    = (lane & 7) + ((lane >> 4) & 1) * 8;
    const int v_ksel = (lane >> 3) & 1;

    auto prefetch = [&](int st, int b, int kc) {
        uint32_t so = sb + OFF_ST + st * ST_STRIDE;
        const __half* kp = gk + (size_t)(b * TT + kc * 64) * HH;
        const __half* vp = gv + (size_t)b * HH * TT + (size_t)kc * 64;
#pragma unroll
        for (int i = 0; i < 2; i++) {
            int idx = tid + i * 256;
            int r = idx >> 3, c = idx & 7;
            uint32_t d = r * UPITCH + c * 16;
            cp16(so + ST_K + d, kp + (size_t)r * HH + c * 8);
            cp16(so + ST_V + d, vp + (size_t)r * TT + c * 8);
        }
    };

    {
        int b, qt, kc;
        decode_unit(u0, b, qt, kc);
        prefetch(u0 & 1, b, kc);
        CP_COMMIT();
        if (u0 + 1 < u1) {
            decode_unit(u0 + 1, b, qt, kc);
            prefetch((u0 + 1) & 1, b, kc);
        }
        CP_COMMIT();
    }

    float of[8][4];
    float lsum0 = 0.f, lsum1 = 0.f;
    int cur_b = -1, cur_qt = -1;

    auto flush = [&](int cb, int cq) {
        float s0 = lsum0, s1 = lsum1;
#pragma unroll
        for (int d = 1; d < 4; d <<= 1) {
            s0 += __shfl_xor_sync(0xffffffffu, s0, d);
            s1 += __shfl_xor_sync(0xffffffffu, s1, d);
        }
        int qb = cb * TT + cq * 128;
        int row0 = qb + wid * 16 + (lane >> 2);
        if ((lane & 3) == 0) {
            atomicAdd(&g_lacc[row0], s0);
            atomicAdd(&g_lacc[row0 + 8], s1);
        }
#pragma unroll
        for (int n8 = 0; n8 < 8; n8++) {
            int col = n8 * 8 + (lane & 3) * 2;
            atomicAdd(&g_oacc[(size_t)row0 * HH + col],           of[n8][0]);
            atomicAdd(&g_oacc[(size_t)row0 * HH + col + 1],       of[n8][1]);
            atomicAdd(&g_oacc[(size_t)(row0 + 8) * HH + col],     of[n8][2]);
            atomicAdd(&g_oacc[(size_t)(row0 + 8) * HH + col + 1], of[n8][3]);
        }
    };

    for (int u = u0; u < u1; u++) {
        int b, qt, kc;
        decode_unit(u, b, qt, kc);

        CP_WAIT1();
        __syncthreads();

        if (b != cur_b || qt != cur_qt) {
            if (cur_qt >= 0) flush(cur_b, cur_qt);
#pragma unroll
            for (int i = 0; i < 8; i++)
#pragma unroll
                for (int j = 0; j < 4; j++) of[i][j] = 0.f;
            lsum0 = lsum1 = 0.f;
            const __half* qp = gq + (size_t)(b * TT + qt * 128) * HH;
#pragma unroll
            for (int i = 0; i < 4; i++) {
                int idx = tid + i * 256;
                int r = idx >> 3, c = idx & 7;
                *(uint4*)(smem + OFF_Q + r * UPITCH + c * 16) =
                    *(const uint4*)(qp + (size_t)r * HH + c * 8);
            }
            __syncthreads();
            cur_b = b; cur_qt = qt;
        }

        const uint32_t so = sb + OFF_ST + (u & 1) * ST_STRIDE;

        // ---- S = Q K^T (single fp16 pass) ----
        float sf[8][4];
#pragma unroll
        for (int i = 0; i < 8; i++)
#pragma unroll
            for (int j = 0; j < 4; j++) sf[i][j] = 0.f;

#pragma unroll
        for (int ks = 0; ks < 4; ks++) {
            uint32_t qa[4];
            ldsm4(qa, q_base + ks * 32);
#pragma unroll
            for (int g = 0; g < 4; g++) {
                uint32_t bh[4];
                ldsm4(bh, so + ST_K + (16 * g + b_key) * UPITCH +
                          ks * 32 + b_hsel * 16);
                mma16816(sf[2 * g],     qa, bh[0], bh[1]);
                mma16816(sf[2 * g + 1], qa, bh[2], bh[3]);
            }
        }

        // ---- fused softmax + PV per 16-column P chunk (single pass) ----
        const bool needmask = (kc >= 2 * qt);
        const int qrow0 = qt * 128 + wid * 16 + (lane >> 2);
        const int keyb  = kc * 64 + (lane & 3) * 2;
#pragma unroll
        for (int pks = 0; pks < 4; pks++) {
            uint32_t pah[4];
#pragma unroll
            for (int h = 0; h < 2; h++) {
                const int n8 = 2 * pks + h;
                int k0 = keyb + n8 * 8;
                float p0 = fast_ex2(sf[n8][0]);
                float p1 = fast_ex2(sf[n8][1]);
                float p2 = fast_ex2(sf[n8][2]);
                float p3 = fast_ex2(sf[n8][3]);
                if (needmask) {
                    if (k0     > qrow0)     p0 = 0.f;
                    if (k0 + 1 > qrow0)     p1 = 0.f;
                    if (k0     > qrow0 + 8) p2 = 0.f;
                    if (k0 + 1 > qrow0 + 8) p3 = 0.f;
                }
                uint32_t a01 = packf16(p0, p1);
                uint32_t a23 = packf16(p2, p3);
                // consistent normalization: sum the ROUNDED p
                __half2 h01 = *(__half2*)&a01;
                __half2 h23 = *(__half2*)&a23;
                lsum0 += __low2float(h01) + __high2float(h01);
                lsum1 += __low2float(h23) + __high2float(h23);
                pah[2 * h]     = a01;
                pah[2 * h + 1] = a23;
            }
#pragma unroll
            for (int g = 0; g < 4; g++) {
                uint32_t vh[4];
                ldsm4(vh, so + ST_V + (16 * g + v_h) * UPITCH +
                          pks * 32 + v_ksel * 16);
                mma16816(of[2 * g],     pah, vh[0], vh[1]);
                mma16816(of[2 * g + 1], pah, vh[2], vh[3]);
            }
        }

        __syncthreads();
        if (u + 2 < u1) {
            int nb, nqt, nkc;
            decode_unit(u + 2, nb, nqt, nkc);
            prefetch(u & 1, nb, nkc);
        }
        CP_COMMIT();
    }

    flush(cur_b, cur_qt);
}

// ---------------------------------------------------------------------------
// finalize: out = O_acc / l
// ---------------------------------------------------------------------------
__global__ __launch_bounds__(256) void finalize(float* __restrict__ out)
{
    int i = blockIdx.x * 256 + threadIdx.x;
    float4 o = ((const float4*)g_oacc)[i];
    float inv = 1.0f / g_lacc[i >> 4];
    o.x *= inv; o.y *= inv; o.z *= inv; o.w *= inv;
    ((float4*)out)[i] = o;
}

// ---------------------------------------------------------------------------
extern "C" void kernel_launch(void* const* d_in, const int* in_sizes, int n_in,
                              void* d_out, int out_size)
{
    const float* x  = (const float*)d_in[0];
    const float* Wq = (const float*)d_in[1];
    const float* Wk = (const float*)d_in[2];
    const float* Wv = (const float*)d_in[3];
    float* out = (float*)d_out;

    cudaFuncSetAttribute(qkv3_kernel,
                         cudaFuncAttributeMaxDynamicSharedMemorySize, QKV3_SMEM);
    cudaFuncSetAttribute(attn_kernel,
                         cudaFuncAttributeMaxDynamicSharedMemorySize, ATT_SMEM);

    dim3 pw_grid(16, 3);
    prep_w<<<pw_grid, 256>>>(Wq, Wk, Wv);

    qkv3_kernel<<<MM / QKV_ROWS, 256, QKV3_SMEM>>>(x);

    zero_acc<<<MM * HH / 4 / 256, 256>>>();

    attn_kernel<<<ATT_NCTA, 256, ATT_SMEM>>>();

    finalize<<<MM * HH / 4 / 256, 256>>>(out);
}